// round 16
// baseline (speedup 1.0000x reference)
#include <cuda_runtime.h>
#include <cstdint>

#define BB 64
#define CC 4096
#define IND 512
#define OO 16
#define TI 32                 // i-tile: full 128B per (b,c) row
#define NTILES (IND / TI)     // 16
#define NCAPW 4               // capsules per WARP
#define WARPS 4
#define NTH (32 * WARPS)
#define CAPS_CTA (NCAPW * WARPS)   // 16
#define BH 32                 // b-rows per CTA (TLB page-set split)
#define PIPE 2

#define XSTG 4096             // x: 32 rows x 4 caps x 32 words (16 KB)
#define WSTG 2048             // W: 4 caps x 32 i x 16 o (8 KB)
#define STG (XSTG + WSTG)     // 6144 floats = 24 KB per warp-stage
#define SMEM_FLOATS (PIPE * WARPS * STG)   // 49152 floats = 192 KB

// ---- packed f32x2 helpers ----
__device__ __forceinline__ uint64_t pack_dup(float x) {
    uint64_t r;
    asm("mov.b64 %0, {%1, %1};" : "=l"(r) : "f"(x));
    return r;
}
__device__ __forceinline__ void fma2(uint64_t& d, uint64_t a, uint64_t b) {
    asm("fma.rn.f32x2 %0, %1, %2, %0;" : "+l"(d) : "l"(a), "l"(b));
}
__device__ __forceinline__ void unpack2(uint64_t v, float& lo, float& hi) {
    asm("mov.b64 {%0, %1}, %2;" : "=f"(lo), "=f"(hi) : "l"(v));
}

// ---- cp.async 16B, L1-bypass ----
__device__ __forceinline__ void cp16(void* dst_smem, const void* src) {
    uint32_t d = (uint32_t)__cvta_generic_to_shared(dst_smem);
    asm volatile("cp.async.cg.shared.global [%0], [%1], 16;"
                 :: "r"(d), "l"(src) : "memory");
}
__device__ __forceinline__ void cp_commit() {
    asm volatile("cp.async.commit_group;" ::: "memory");
}
__device__ __forceinline__ void cp_wait1() {
    asm volatile("cp.async.wait_group 1;" ::: "memory");
}
__device__ __forceinline__ void cp_wait0() {
    asm volatile("cp.async.wait_group 0;" ::: "memory");
}

extern __shared__ float sm[];

__global__ __launch_bounds__(NTH)
void primarycaps_kernel(const float* __restrict__ x,
                        const float* __restrict__ W,
                        const float* __restrict__ bias,
                        float* __restrict__ out)
{
    const int t    = threadIdx.x;
    const int wid  = t >> 5;
    const int lane = t & 31;

    // b-half is the FAST grid axis: the two CTAs sharing this W slice are
    // linear neighbors -> same wave -> second W read hits L2 (proven R12).
    const int c0 = blockIdx.y * CAPS_CTA + wid * NCAPW;  // warp's 4 caps
    const int b0 = blockIdx.x * BH;                      // CTA's b-half

    // compute map: mb=8 (rows tb+4k, k=0..7), nb=8 (o-half), cap
    const int tb  = lane & 3;         // b-group 0..3
    const int to  = (lane >> 2) & 1;  // o-half
    const int cap = lane >> 3;        // capsule 0..3

    // x staging map: one instr = 4 rows x 8 chunks = 4 full 128B lines
    const int srow = lane >> 3;       // local row 0..3
    const int sch  = lane & 7;        // 16B chunk 0..7

    // per-warp smem stage bases
    float* const stg0 = sm + (0 * WARPS + wid) * STG;
    float* const stg1 = sm + (1 * WARPS + wid) * STG;

    // ---- accumulators: 8 b-rows x 4 o-pairs (packed f32x2) ----
    uint64_t acc[8][4];
    #pragma unroll
    for (int k = 0; k < 8; ++k)
        #pragma unroll
        for (int j = 0; j < 4; ++j)
            acc[k][j] = 0ULL;

    // ---- stage helper: tile jt into buffer bf (this warp only) ----
    // x layout: interleaved rows R = row*4 + cap, 32 words each, chunk
    // position = ch ^ (R & 7) (= ch ^ (4*(row&1)+cap)) -> <=2-way banks.
    auto stage = [&](int bf, int jt) {
        float* dx = bf ? stg1 : stg0;
        #pragma unroll
        for (int cc = 0; cc < NCAPW; ++cc) {
            #pragma unroll
            for (int g = 0; g < 8; ++g) {
                const int row = g * 4 + srow;          // 0..31
                const int R   = row * 4 + cc;
                cp16(&dx[R * 32 + ((sch ^ (R & 7)) * 4)],
                     x + ((size_t)(b0 + row) * CC + c0 + cc) * IND
                       + (size_t)jt * TI + sch * 4);
            }
        }
        // W: per cap 2KB contiguous (linear layout), 4 instrs of 512B
        float* dw = (bf ? stg1 : stg0) + XSTG;
        #pragma unroll
        for (int cc = 0; cc < NCAPW; ++cc) {
            #pragma unroll
            for (int m = 0; m < 4; ++m) {
                const int ofs = m * 128 + lane * 4;
                cp16(&dw[cc * 512 + ofs],
                     W + ((size_t)(c0 + cc) * IND + (size_t)jt * TI) * OO + ofs);
            }
        }
        cp_commit();
    };

    // ---- prologue ----
    stage(0, 0);

    // per-lane constant chunk-xor for compute x reads
    const int xr = 4 * (tb & 1) + cap;

    for (int j = 0; j < NTILES; ++j) {
        if (j + 1 < NTILES) {
            stage((j + 1) & 1, j + 1);
            cp_wait1();
        } else {
            cp_wait0();
        }
        __syncwarp();

        const float* __restrict__ xb = (j & 1) ? stg1 : stg0;
        const float* __restrict__ wb = ((j & 1) ? stg1 : stg0) + XSTG + cap * 512;

        #pragma unroll
        for (int q = 0; q < 8; ++q) {           // 8 chunks of 4 i
            float4 xv[8];
            #pragma unroll
            for (int k = 0; k < 8; ++k) {
                const int R = (tb + 4 * k) * 4 + cap;
                xv[k] = *(const float4*)&xb[R * 32 + ((q ^ xr) * 4)];
            }

            #pragma unroll
            for (int r = 0; r < 4; ++r) {
                const int i = q * 4 + r;
                const ulonglong2 wA =
                    *(const ulonglong2*)&wb[i * OO + to * 8];
                const ulonglong2 wB =
                    *(const ulonglong2*)&wb[i * OO + to * 8 + 4];

                #pragma unroll
                for (int k = 0; k < 8; ++k) {
                    const float xs = (r == 0) ? xv[k].x :
                                     (r == 1) ? xv[k].y :
                                     (r == 2) ? xv[k].z : xv[k].w;
                    const uint64_t xd = pack_dup(xs);
                    fma2(acc[k][0], xd, wA.x);
                    fma2(acc[k][1], xd, wA.y);
                    fma2(acc[k][2], xd, wB.x);
                    fma2(acc[k][3], xd, wB.y);
                }
            }
        }
        __syncwarp();   // warp done reading buffer before it is refilled
    }

    // ---- epilogue ----
    const int c  = c0 + cap;
    const int o0 = to * 8;
    const float4* bias4 = (const float4*)(bias + (size_t)c * OO + o0);
    const float4 bz0 = bias4[0];
    const float4 bz1 = bias4[1];

    #pragma unroll
    for (int k = 0; k < 8; ++k) {
        float v0, v1, v2, v3, v4, v5, v6, v7;
        unpack2(acc[k][0], v0, v1);
        unpack2(acc[k][1], v2, v3);
        unpack2(acc[k][2], v4, v5);
        unpack2(acc[k][3], v6, v7);

        float4 lo = make_float4(v0 + bz0.x, v1 + bz0.y, v2 + bz0.z, v3 + bz0.w);
        float4 hi = make_float4(v4 + bz1.x, v5 + bz1.y, v6 + bz1.z, v7 + bz1.w);

        const int b = b0 + tb + 4 * k;
        float* op = out + ((size_t)b * CC + c) * OO + o0;
        *(float4*)(op)     = lo;
        *(float4*)(op + 4) = hi;
    }
}

extern "C" void kernel_launch(void* const* d_in, const int* in_sizes, int n_in,
                              void* d_out, int out_size)
{
    (void)in_sizes; (void)n_in; (void)out_size;
    const float* x    = (const float*)d_in[0];
    const float* W    = (const float*)d_in[1];
    const float* bias = (const float*)d_in[2];
    float*       out  = (float*)d_out;

    const int smem_bytes = SMEM_FLOATS * sizeof(float);   // 192 KB
    static bool attr_done = false;
    if (!attr_done) {
        cudaFuncSetAttribute(primarycaps_kernel,
                             cudaFuncAttributeMaxDynamicSharedMemorySize,
                             smem_bytes);
        attr_done = true;
    }
    dim3 grid(BB / BH, CC / CAPS_CTA);   // (2, 256): b-half is the FAST axis
    primarycaps_kernel<<<grid, NTH, smem_bytes>>>(x, W, bias, out);
}

// round 17
// speedup vs baseline: 1.6189x; 1.6189x over previous
#include <cuda_runtime.h>
#include <cstdint>

#define BB 64
#define CC 4096
#define IND 512
#define OO 16
#define TI 32                 // i-tile: full 128B per (b,c) row
#define NTILES (IND / TI)     // 16
#define NCAPW 4               // capsules per WARP
#define WARPS 4
#define NTH (32 * WARPS)
#define CAPS_CTA (NCAPW * WARPS)   // 16
#define BH 32                 // b-rows per CTA (TLB page-set split)
#define PIPE 2

#define XSTG 4096             // x: 32 rows x 4 caps x 32 words (16 KB)
#define WSTG 2048             // W: 4 caps x 32 i x 16 o (8 KB)
#define STG (XSTG + WSTG)     // 6144 floats = 24 KB per warp-stage
#define SMEM_FLOATS (PIPE * WARPS * STG)   // 49152 floats = 192 KB

// ---- packed f32x2 helpers ----
__device__ __forceinline__ uint64_t pack_dup(float x) {
    uint64_t r;
    asm("mov.b64 %0, {%1, %1};" : "=l"(r) : "f"(x));
    return r;
}
__device__ __forceinline__ void fma2(uint64_t& d, uint64_t a, uint64_t b) {
    asm("fma.rn.f32x2 %0, %1, %2, %0;" : "+l"(d) : "l"(a), "l"(b));
}
__device__ __forceinline__ void unpack2(uint64_t v, float& lo, float& hi) {
    asm("mov.b64 {%0, %1}, %2;" : "=f"(lo), "=f"(hi) : "l"(v));
}

// ---- cp.async 16B, L1-bypass ----
__device__ __forceinline__ void cp16(void* dst_smem, const void* src) {
    uint32_t d = (uint32_t)__cvta_generic_to_shared(dst_smem);
    asm volatile("cp.async.cg.shared.global [%0], [%1], 16;"
                 :: "r"(d), "l"(src) : "memory");
}
__device__ __forceinline__ void cp_commit() {
    asm volatile("cp.async.commit_group;" ::: "memory");
}
__device__ __forceinline__ void cp_wait1() {
    asm volatile("cp.async.wait_group 1;" ::: "memory");
}
__device__ __forceinline__ void cp_wait0() {
    asm volatile("cp.async.wait_group 0;" ::: "memory");
}

extern __shared__ float sm[];

__global__ __launch_bounds__(NTH)
void primarycaps_kernel(const float* __restrict__ x,
                        const float* __restrict__ W,
                        const float* __restrict__ bias,
                        float* __restrict__ out)
{
    const int t    = threadIdx.x;
    const int wid  = t >> 5;
    const int lane = t & 31;

    // b-half is the FAST grid axis: the two CTAs sharing this W slice are
    // linear neighbors -> same wave -> second W read hits L2 (proven R12).
    const int c0 = blockIdx.y * CAPS_CTA + wid * NCAPW;  // warp's 4 caps
    const int b0 = blockIdx.x * BH;                      // CTA's b-half

    // compute map: mb=8 (rows tb+4k, k=0..7), nb=8 (o-half), cap
    const int tb  = lane & 3;         // b-group 0..3
    const int to  = (lane >> 2) & 1;  // o-half
    const int cap = lane >> 3;        // capsule 0..3

    // x staging map: one instr = 4 rows x 8 chunks = 4 full 128B lines
    const int srow = lane >> 3;       // local row 0..3
    const int sch  = lane & 7;        // 16B chunk 0..7

    // per-warp smem stage bases
    float* const stg0 = sm + (0 * WARPS + wid) * STG;
    float* const stg1 = sm + (1 * WARPS + wid) * STG;

    // ---- accumulators: 8 b-rows x 4 o-pairs (packed f32x2) ----
    uint64_t acc[8][4];
    #pragma unroll
    for (int k = 0; k < 8; ++k)
        #pragma unroll
        for (int j = 0; j < 4; ++j)
            acc[k][j] = 0ULL;

    // ---- stage helper: tile jt into buffer bf (this warp only) ----
    // x layout: interleaved rows R = row*4 + cap, 32 words each, chunk
    // position = ch ^ (R & 7) (= ch ^ (4*(row&1)+cap)) -> <=2-way banks.
    auto stage = [&](int bf, int jt) {
        float* dx = bf ? stg1 : stg0;
        #pragma unroll
        for (int cc = 0; cc < NCAPW; ++cc) {
            #pragma unroll
            for (int g = 0; g < 8; ++g) {
                const int row = g * 4 + srow;          // 0..31
                const int R   = row * 4 + cc;
                cp16(&dx[R * 32 + ((sch ^ (R & 7)) * 4)],
                     x + ((size_t)(b0 + row) * CC + c0 + cc) * IND
                       + (size_t)jt * TI + sch * 4);
            }
        }
        // W: per cap 2KB contiguous (linear layout), 4 instrs of 512B
        float* dw = (bf ? stg1 : stg0) + XSTG;
        #pragma unroll
        for (int cc = 0; cc < NCAPW; ++cc) {
            #pragma unroll
            for (int m = 0; m < 4; ++m) {
                const int ofs = m * 128 + lane * 4;
                cp16(&dw[cc * 512 + ofs],
                     W + ((size_t)(c0 + cc) * IND + (size_t)jt * TI) * OO + ofs);
            }
        }
        cp_commit();
    };

    // ---- prologue ----
    stage(0, 0);

    // per-lane constant chunk-xor for compute x reads
    const int xr = 4 * (tb & 1) + cap;

    for (int j = 0; j < NTILES; ++j) {
        if (j + 1 < NTILES) {
            stage((j + 1) & 1, j + 1);
            cp_wait1();
        } else {
            cp_wait0();
        }
        __syncwarp();

        const float* __restrict__ xb = (j & 1) ? stg1 : stg0;
        const float* __restrict__ wb = ((j & 1) ? stg1 : stg0) + XSTG + cap * 512;

        #pragma unroll
        for (int q = 0; q < 8; ++q) {           // 8 chunks of 4 i
            float4 xv[8];
            #pragma unroll
            for (int k = 0; k < 8; ++k) {
                const int R = (tb + 4 * k) * 4 + cap;
                xv[k] = *(const float4*)&xb[R * 32 + ((q ^ xr) * 4)];
            }

            #pragma unroll
            for (int r = 0; r < 4; ++r) {
                const int i = q * 4 + r;
                const ulonglong2 wA =
                    *(const ulonglong2*)&wb[i * OO + to * 8];
                const ulonglong2 wB =
                    *(const ulonglong2*)&wb[i * OO + to * 8 + 4];

                #pragma unroll
                for (int k = 0; k < 8; ++k) {
                    const float xs = (r == 0) ? xv[k].x :
                                     (r == 1) ? xv[k].y :
                                     (r == 2) ? xv[k].z : xv[k].w;
                    const uint64_t xd = pack_dup(xs);
                    fma2(acc[k][0], xd, wA.x);
                    fma2(acc[k][1], xd, wA.y);
                    fma2(acc[k][2], xd, wB.x);
                    fma2(acc[k][3], xd, wB.y);
                }
            }
        }
        __syncwarp();   // warp done reading buffer before it is refilled
    }

    // ---- epilogue ----
    const int c  = c0 + cap;
    const int o0 = to * 8;
    const float4* bias4 = (const float4*)(bias + (size_t)c * OO + o0);
    const float4 bz0 = bias4[0];
    const float4 bz1 = bias4[1];

    #pragma unroll
    for (int k = 0; k < 8; ++k) {
        float v0, v1, v2, v3, v4, v5, v6, v7;
        unpack2(acc[k][0], v0, v1);
        unpack2(acc[k][1], v2, v3);
        unpack2(acc[k][2], v4, v5);
        unpack2(acc[k][3], v6, v7);

        float4 lo = make_float4(v0 + bz0.x, v1 + bz0.y, v2 + bz0.z, v3 + bz0.w);
        float4 hi = make_float4(v4 + bz1.x, v5 + bz1.y, v6 + bz1.z, v7 + bz1.w);

        const int b = b0 + tb + 4 * k;
        float* op = out + ((size_t)b * CC + c) * OO + o0;
        *(float4*)(op)     = lo;
        *(float4*)(op + 4) = hi;
    }
}

extern "C" void kernel_launch(void* const* d_in, const int* in_sizes, int n_in,
                              void* d_out, int out_size)
{
    (void)in_sizes; (void)n_in; (void)out_size;
    const float* x    = (const float*)d_in[0];
    const float* W    = (const float*)d_in[1];
    const float* bias = (const float*)d_in[2];
    float*       out  = (float*)d_out;

    const int smem_bytes = SMEM_FLOATS * sizeof(float);   // 192 KB
    static bool attr_done = false;
    if (!attr_done) {
        cudaFuncSetAttribute(primarycaps_kernel,
                             cudaFuncAttributeMaxDynamicSharedMemorySize,
                             smem_bytes);
        attr_done = true;
    }
    dim3 grid(BB / BH, CC / CAPS_CTA);   // (2, 256): b-half is the FAST axis
    primarycaps_kernel<<<grid, NTH, smem_bytes>>>(x, W, bias, out);
}